// round 15
// baseline (speedup 1.0000x reference)
#include <cuda_runtime.h>
#include <cuda_fp16.h>
#include <cstdint>

#define N_NODES 100000
#define HID     128
#define FEAT    256
#define BSLOT   64   // bucket capacity; max degree ~45 for Poisson(16)

// Scratch (allocation-free rule: __device__ globals)
__device__ __align__(16) __half g_h[(size_t)N_NODES * HID];    // fp16 h
__device__ __align__(16) __half g_x16[(size_t)N_NODES * FEAT]; // fp16 X
__device__ __align__(16) __half g_wt16[(size_t)HID * FEAT];    // W^T, fp16
__device__ int   g_cnt[N_NODES];
__device__ int   g_cur[N_NODES];
__device__ float g_dis[N_NODES];
__device__ int   g_bkt[(size_t)N_NODES * BSLOT];
__device__ int   g_is64;

// Side stream + fork/join events, created at static-init time.
struct SideStream {
    cudaStream_t s;
    cudaEvent_t  fork, join;
    SideStream() {
        cudaStreamCreateWithFlags(&s, cudaStreamNonBlocking);
        cudaEventCreateWithFlags(&fork, cudaEventDisableTiming);
        cudaEventCreateWithFlags(&join, cudaEventDisableTiming);
    }
};
static SideStream g_ss;

__device__ __forceinline__ uint32_t smem_u32(const void* p) {
    uint32_t a;
    asm("{ .reg .u64 t; cvta.to.shared.u64 t, %1; cvt.u32.u64 %0, t; }" : "=r"(a) : "l"(p));
    return a;
}
__device__ __forceinline__ void cp_async16(uint32_t saddr, const void* g, int srcsize) {
    asm volatile("cp.async.cg.shared.global [%0], [%1], 16, %2;"
                 :: "r"(saddr), "l"(g), "r"(srcsize) : "memory");
}
#define CP_COMMIT()  asm volatile("cp.async.commit_group;" ::: "memory")
#define CP_WAIT(n)   asm volatile("cp.async.wait_group %0;" :: "n"(n) : "memory")

__device__ __forceinline__ void ldsm_x4(uint32_t& r0, uint32_t& r1, uint32_t& r2, uint32_t& r3,
                                        uint32_t addr) {
    asm volatile("ldmatrix.sync.aligned.m8n8.x4.shared.b16 {%0,%1,%2,%3}, [%4];"
                 : "=r"(r0), "=r"(r1), "=r"(r2), "=r"(r3) : "r"(addr));
}

// ---------------------------------------------------------------------------
// detect edge dtype + zero cursors (side stream, off critical path)
// ---------------------------------------------------------------------------
__global__ void detect_zero_kernel(const void* __restrict__ ei, int E) {
    int i = blockIdx.x * blockDim.x + threadIdx.x;
    if (i == 0) {
        const long long* p64 = (const long long*)ei;
        int n = E < 64 ? E : 64;
        int ok64 = 1;
        for (int j = 0; j < n; j++) {
            long long v = p64[j];
            if (v < 0 || v >= N_NODES) { ok64 = 0; break; }
        }
        g_is64 = ok64;
    }
    if (i < N_NODES) g_cur[i] = 0;
}

// ---------------------------------------------------------------------------
// Fused prep: X fp32 -> fp16 (streaming, float4 granularity) + W transpose.
// ---------------------------------------------------------------------------
__global__ void xcvt_kernel(const float* __restrict__ X, const float* __restrict__ W) {
    int i = blockIdx.x * blockDim.x + threadIdx.x;
    if (i < N_NODES * FEAT / 4) {
        float4 v = *(const float4*)(X + (size_t)i * 4);
        __half2* p = (__half2*)(g_x16 + (size_t)i * 4);
        p[0] = __floats2half2_rn(v.x, v.y);
        p[1] = __floats2half2_rn(v.z, v.w);
    }
    if (i < FEAT * HID) {
        int k = i >> 7, n = i & (HID - 1);
        g_wt16[(long)n * FEAT + k] = __float2half_rn(W[i]);
    }
}

// ---------------------------------------------------------------------------
// GEMM via mma.sync m16n8k16 fp16 (fp32 accumulate).
// CTA tile 128x128, 8 warps (4M x 2N), warp tile 32x64. K chunked by 32.
// BOTH operands cp.async fp16 (A from g_x16: L2-resident, written by xcvt).
// Fragment loads via ldmatrix.x4. No register staging, no in-kernel cvt.
// ---------------------------------------------------------------------------
#define BKC     32
#define HPITCH  40
#define NCH     (FEAT / BKC)       // 8
#define STAGEH  (128 * HPITCH)     // halves per stage

__global__ void __launch_bounds__(256, 2) gemm_mma_kernel(int M) {
    __shared__ __half As[2 * STAGEH];
    __shared__ __half Bs[2 * STAGEH];
    const uint32_t as_base = smem_u32(As);
    const uint32_t bs_base = smem_u32(Bs);

    const int tid = threadIdx.x, lane = tid & 31, wid = tid >> 5;
    const long m0 = (long)blockIdx.x * 128;
    const int mrow0 = (wid & 3) * 32;
    const int ncol0 = (wid >> 2) * 64;
    const int tig = lane & 3, grp = lane >> 2;

    // ldmatrix lane-address offsets (in halves).
    uint32_t aoff[2];
    {
        int rrow = (lane & 7) + ((lane >> 3) & 1) * 8;
        int rcol = (lane >> 4) * 8;
        #pragma unroll
        for (int mt = 0; mt < 2; mt++)
            aoff[mt] = (mrow0 + mt * 16 + rrow) * HPITCH + rcol;
    }
    uint32_t boff[4];
    {
        int nrow = ((lane >> 4) & 1) * 8 + (lane & 7);
        int ncol = ((lane >> 3) & 1) * 8;
        #pragma unroll
        for (int np = 0; np < 4; np++)
            boff[np] = (ncol0 + np * 16 + nrow) * HPITCH + ncol;
    }

    // One chunk = one cp.async group: A (128 rows x 64 B) + B (128 rows x 64 B).
    auto cpChunk = [&](int c, int s) {
        #pragma unroll
        for (int l = 0; l < 2; l++) {
            int idx = tid + l * 256;          // 0..511
            int r = idx >> 2, j = idx & 3;    // row, 16B-piece
            long gr = m0 + r;
            int ok = (gr < M) ? 16 : 0;
            long gc = (gr < M) ? gr : (M - 1);
            cp_async16(as_base + (s * STAGEH + r * HPITCH + j * 8) * 2,
                       g_x16 + gc * FEAT + c * BKC + j * 8, ok);
        }
        #pragma unroll
        for (int l = 0; l < 2; l++) {
            int idx = tid + l * 256;
            int n = idx >> 2, j = idx & 3;
            cp_async16(bs_base + (s * STAGEH + n * HPITCH + j * 8) * 2,
                       g_wt16 + (long)n * FEAT + c * BKC + j * 8, 16);
        }
        CP_COMMIT();
    };

    float acc[2][8][4];
    #pragma unroll
    for (int mt = 0; mt < 2; mt++)
        #pragma unroll
        for (int nt = 0; nt < 8; nt++)
            #pragma unroll
            for (int q = 0; q < 4; q++) acc[mt][nt][q] = 0.0f;

    cpChunk(0, 0);
    cpChunk(1, 1);

    for (int c = 0; c < NCH; c++) {
        const int s = c & 1;
        if (c + 1 < NCH) CP_WAIT(1); else CP_WAIT(0);
        __syncthreads();

        const uint32_t abase = as_base + s * STAGEH * 2;
        const uint32_t bbase = bs_base + s * STAGEH * 2;

        #pragma unroll
        for (int ks = 0; ks < 2; ks++) {
            const int k0h = ks * 16 * 2;
            uint32_t a[2][4], b[8][2];
            #pragma unroll
            for (int mt = 0; mt < 2; mt++)
                ldsm_x4(a[mt][0], a[mt][1], a[mt][2], a[mt][3],
                        abase + aoff[mt] * 2 + k0h);
            #pragma unroll
            for (int np = 0; np < 4; np++)
                ldsm_x4(b[2*np][0], b[2*np][1], b[2*np+1][0], b[2*np+1][1],
                        bbase + boff[np] * 2 + k0h);
            #pragma unroll
            for (int mt = 0; mt < 2; mt++)
                #pragma unroll
                for (int nt = 0; nt < 8; nt++)
                    asm volatile(
                        "mma.sync.aligned.m16n8k16.row.col.f32.f16.f16.f32 "
                        "{%0,%1,%2,%3}, {%4,%5,%6,%7}, {%8,%9}, {%0,%1,%2,%3};"
                        : "+f"(acc[mt][nt][0]), "+f"(acc[mt][nt][1]),
                          "+f"(acc[mt][nt][2]), "+f"(acc[mt][nt][3])
                        : "r"(a[mt][0]), "r"(a[mt][1]), "r"(a[mt][2]), "r"(a[mt][3]),
                          "r"(b[nt][0]), "r"(b[nt][1]));
        }
        __syncthreads();
        if (c + 2 < NCH) cpChunk(c + 2, s);
    }

    #pragma unroll
    for (int mt = 0; mt < 2; mt++) {
        long r0 = m0 + mrow0 + mt * 16 + grp;
        long r1 = r0 + 8;
        #pragma unroll
        for (int nt = 0; nt < 8; nt++) {
            int col = ncol0 + nt * 8 + 2 * tig;
            if (r0 < M)
                *(__half2*)(g_h + r0 * HID + col) =
                    __floats2half2_rn(acc[mt][nt][0], acc[mt][nt][1]);
            if (r1 < M)
                *(__half2*)(g_h + r1 * HID + col) =
                    __floats2half2_rn(acc[mt][nt][2], acc[mt][nt][3]);
        }
    }
}

// ---------------------------------------------------------------------------
// Bucketed adjacency fill: 2 edges per thread, vectorized index loads.
// ---------------------------------------------------------------------------
__global__ void fill_kernel(const void* __restrict__ ei, int E) {
    int t = blockIdx.x * blockDim.x + threadIdx.x;
    long e0 = (long)t * 2;
    if (e0 >= E) return;
    int is64 = g_is64;

    int r0, r1, c0, c1;
    bool two = (e0 + 1 < E);
    if (is64) {
        const long long* p = (const long long*)ei;
        if (two) {
            longlong2 rv = *(const longlong2*)(p + e0);
            longlong2 cv = *(const longlong2*)(p + E + e0);
            r0 = (int)rv.x; r1 = (int)rv.y; c0 = (int)cv.x; c1 = (int)cv.y;
        } else {
            r0 = (int)p[e0]; c0 = (int)p[E + e0]; r1 = -1; c1 = -1;
        }
    } else {
        const int* p = (const int*)ei;
        if (two) {
            int2 rv = *(const int2*)(p + e0);
            int2 cv = *(const int2*)(p + E + e0);
            r0 = rv.x; r1 = rv.y; c0 = cv.x; c1 = cv.y;
        } else {
            r0 = p[e0]; c0 = p[E + e0]; r1 = -1; c1 = -1;
        }
    }

    if ((unsigned)r0 < (unsigned)N_NODES && (unsigned)c0 < (unsigned)N_NODES) {
        int pos = atomicAdd(&g_cur[r0], 1);
        if (pos < BSLOT) g_bkt[(long)r0 * BSLOT + pos] = c0;
    }
    if (two && (unsigned)r1 < (unsigned)N_NODES && (unsigned)c1 < (unsigned)N_NODES) {
        int pos = atomicAdd(&g_cur[r1], 1);
        if (pos < BSLOT) g_bkt[(long)r1 * BSLOT + pos] = c1;
    }
}

__global__ void invsqrt_kernel() {
    int i = blockIdx.x * blockDim.x + threadIdx.x;
    if (i >= N_NODES) return;
    int c = g_cur[i];
    g_cnt[i] = c < BSLOT ? c : BSLOT;
    g_dis[i] = (c > 0) ? rsqrtf((float)c) : 0.0f;
}

// ---------------------------------------------------------------------------
// Aggregate: one warp per node; paired edges (lanes 0-15 edge j, 16-31 edge
// j+1), uint4 gathers (8 cols/lane), fp32 accumulate, cross-half combine.
// out[r] = bias + dis[r] * sum_c dis[c] * h[c]
// ---------------------------------------------------------------------------
__global__ void __launch_bounds__(256) agg_kernel(float* __restrict__ out,
                                                  const float* __restrict__ bias) {
    int r    = blockIdx.x * 8 + (threadIdx.x >> 5);
    int lane = threadIdx.x & 31;
    if (r >= N_NODES) return;

    const int   cnt = g_cnt[r];
    const float dr  = g_dis[r];
    const int*  row = g_bkt + (long)r * BSLOT;

    const int half    = lane >> 4;        // 0: even edges, 1: odd edges
    const int sublane = lane & 15;        // owns cols sublane*8 .. +7

    float acc[8];
    #pragma unroll
    for (int q = 0; q < 8; q++) acc[q] = 0.0f;

    for (int base = 0; base < cnt; base += 32) {
        int  k  = base + lane;
        bool ok = k < cnt;
        int  c  = ok ? row[k] : 0;
        float w = ok ? g_dis[c] : 0.0f;
        int nn = cnt - base; if (nn > 32) nn = 32;
        #pragma unroll 2
        for (int j = 0; j < nn; j += 2) {
            int   c0 = __shfl_sync(0xffffffffu, c, j);
            float w0 = __shfl_sync(0xffffffffu, w, j);
            int   c1 = __shfl_sync(0xffffffffu, c, j + 1);  // j+1<=31; zero-padded
            float w1 = __shfl_sync(0xffffffffu, w, j + 1);
            int   mc = half ? c1 : c0;
            float mw = half ? w1 : w0;
            uint4 u = *(const uint4*)(g_h + (long)mc * HID + sublane * 8);
            float2 p0 = __half22float2(*(const __half2*)&u.x);
            float2 p1 = __half22float2(*(const __half2*)&u.y);
            float2 p2 = __half22float2(*(const __half2*)&u.z);
            float2 p3 = __half22float2(*(const __half2*)&u.w);
            acc[0] = fmaf(mw, p0.x, acc[0]);
            acc[1] = fmaf(mw, p0.y, acc[1]);
            acc[2] = fmaf(mw, p1.x, acc[2]);
            acc[3] = fmaf(mw, p1.y, acc[3]);
            acc[4] = fmaf(mw, p2.x, acc[4]);
            acc[5] = fmaf(mw, p2.y, acc[5]);
            acc[6] = fmaf(mw, p3.x, acc[6]);
            acc[7] = fmaf(mw, p3.y, acc[7]);
        }
    }

    // combine even/odd halves
    #pragma unroll
    for (int q = 0; q < 8; q++)
        acc[q] += __shfl_xor_sync(0xffffffffu, acc[q], 16);

    if (half == 0) {
        const float* bp = bias + sublane * 8;
        float* op = out + (long)r * HID + sublane * 8;
        float4 b0 = *(const float4*)(bp);
        float4 b1 = *(const float4*)(bp + 4);
        *(float4*)(op) = make_float4(fmaf(dr, acc[0], b0.x), fmaf(dr, acc[1], b0.y),
                                     fmaf(dr, acc[2], b0.z), fmaf(dr, acc[3], b0.w));
        *(float4*)(op + 4) = make_float4(fmaf(dr, acc[4], b1.x), fmaf(dr, acc[5], b1.y),
                                         fmaf(dr, acc[6], b1.z), fmaf(dr, acc[7], b1.w));
    }
}

// ---------------------------------------------------------------------------
extern "C" void kernel_launch(void* const* d_in, const int* in_sizes, int n_in,
                              void* d_out, int out_size) {
    const float* x    = (const float*)d_in[0];
    const void*  ei   = d_in[1];
    const float* W    = (const float*)d_in[2];
    const float* bias = (const float*)d_in[3];
    float*       out  = (float*)d_out;

    const int E = in_sizes[1] / 2;

    // fork immediately: entire topology branch on side stream
    cudaEventRecord(g_ss.fork, 0);
    cudaStreamWaitEvent(g_ss.s, g_ss.fork, 0);
    detect_zero_kernel<<<(N_NODES + 255) / 256, 256, 0, g_ss.s>>>(ei, E);
    fill_kernel<<<(E / 2 + 255) / 256, 256, 0, g_ss.s>>>(ei, E);
    invsqrt_kernel<<<(N_NODES + 255) / 256, 256, 0, g_ss.s>>>();

    // main stream: X->fp16 + W transpose, then pure-fp16 GEMM
    xcvt_kernel<<<(N_NODES * FEAT / 4 + 255) / 256, 256>>>(x, W);
    gemm_mma_kernel<<<(N_NODES + 127) / 128, 256>>>(N_NODES);

    // join, then aggregate
    cudaEventRecord(g_ss.join, g_ss.s);
    cudaStreamWaitEvent(0, g_ss.join, 0);
    agg_kernel<<<(N_NODES + 7) / 8, 256>>>(out, bias);
}

// round 16
// speedup vs baseline: 1.1536x; 1.1536x over previous
#include <cuda_runtime.h>
#include <cuda_fp16.h>
#include <cstdint>

#define N_NODES 100000
#define HID     128
#define FEAT    256
#define BSLOT   64   // bucket capacity; max degree ~45 for Poisson(16)

// Scratch (allocation-free rule: __device__ globals)
__device__ __align__(16) __half g_h[(size_t)N_NODES * HID];    // fp16 h
__device__ __align__(16) __half g_wt16[(size_t)HID * FEAT];    // W^T, fp16
__device__ int   g_cnt[N_NODES];
__device__ int   g_cur[N_NODES];
__device__ float g_dis[N_NODES];
__device__ int   g_bkt[(size_t)N_NODES * BSLOT];
__device__ int   g_is64;

// Side stream + fork/join events, created at static-init time.
struct SideStream {
    cudaStream_t s;
    cudaEvent_t  fork, join;
    SideStream() {
        cudaStreamCreateWithFlags(&s, cudaStreamNonBlocking);
        cudaEventCreateWithFlags(&fork, cudaEventDisableTiming);
        cudaEventCreateWithFlags(&join, cudaEventDisableTiming);
    }
};
static SideStream g_ss;

__device__ __forceinline__ uint32_t smem_u32(const void* p) {
    uint32_t a;
    asm("{ .reg .u64 t; cvta.to.shared.u64 t, %1; cvt.u32.u64 %0, t; }" : "=r"(a) : "l"(p));
    return a;
}
__device__ __forceinline__ void cp_async16(uint32_t saddr, const void* g, int srcsize) {
    asm volatile("cp.async.cg.shared.global [%0], [%1], 16, %2;"
                 :: "r"(saddr), "l"(g), "r"(srcsize) : "memory");
}
#define CP_COMMIT()  asm volatile("cp.async.commit_group;" ::: "memory")
#define CP_WAIT(n)   asm volatile("cp.async.wait_group %0;" :: "n"(n) : "memory")

__device__ __forceinline__ void ldsm_x4(uint32_t& r0, uint32_t& r1, uint32_t& r2, uint32_t& r3,
                                        uint32_t addr) {
    asm volatile("ldmatrix.sync.aligned.m8n8.x4.shared.b16 {%0,%1,%2,%3}, [%4];"
                 : "=r"(r0), "=r"(r1), "=r"(r2), "=r"(r3) : "r"(addr));
}

// ---------------------------------------------------------------------------
// detect edge dtype + zero cursors (side stream, off critical path)
// ---------------------------------------------------------------------------
__global__ void detect_zero_kernel(const void* __restrict__ ei, int E) {
    int i = blockIdx.x * blockDim.x + threadIdx.x;
    if (i == 0) {
        const long long* p64 = (const long long*)ei;
        int n = E < 64 ? E : 64;
        int ok64 = 1;
        for (int j = 0; j < n; j++) {
            long long v = p64[j];
            if (v < 0 || v >= N_NODES) { ok64 = 0; break; }
        }
        g_is64 = ok64;
    }
    if (i < N_NODES) g_cur[i] = 0;
}

// W [256][128] -> g_wt16 [128][256] fp16
__global__ void transpose_kernel(const float* __restrict__ W) {
    int i = blockIdx.x * blockDim.x + threadIdx.x;
    if (i < FEAT * HID) {
        int k = i >> 7, n = i & (HID - 1);
        g_wt16[(long)n * FEAT + k] = __float2half_rn(W[i]);
    }
}

// ---------------------------------------------------------------------------
// GEMM via mma.sync m16n8k16 fp16 (fp32 accumulate).  [R14 design]
// CTA tile 128x128, 8 warps (4M x 2N), warp tile 32x64. K chunked by 32.
// Fragment loads via ldmatrix.x4.
// A: LDG fp32 -> STS fp16 (reg double-buffer) + L2 prefetch.
// B: cp.async fp16 from g_wt16.
// ---------------------------------------------------------------------------
#define BKC     32
#define HPITCH  40
#define NCH     (FEAT / BKC)       // 8
#define STAGEH  (128 * HPITCH)     // halves per stage

__global__ void __launch_bounds__(256, 2) gemm_mma_kernel(const float* __restrict__ X, int M) {
    __shared__ __half As[2 * STAGEH];
    __shared__ __half Bs[2 * STAGEH];
    const uint32_t as_base = smem_u32(As);
    const uint32_t bs_base = smem_u32(Bs);

    const int tid = threadIdx.x, lane = tid & 31, wid = tid >> 5;
    const long m0 = (long)blockIdx.x * 128;
    const int mrow0 = (wid & 3) * 32;
    const int ncol0 = (wid >> 2) * 64;
    const int tig = lane & 3, grp = lane >> 2;

    uint32_t aoff[2];
    {
        int rrow = (lane & 7) + ((lane >> 3) & 1) * 8;
        int rcol = (lane >> 4) * 8;
        #pragma unroll
        for (int mt = 0; mt < 2; mt++)
            aoff[mt] = (mrow0 + mt * 16 + rrow) * HPITCH + rcol;
    }
    uint32_t boff[4];
    {
        int nrow = ((lane >> 4) & 1) * 8 + (lane & 7);
        int ncol = ((lane >> 3) & 1) * 8;
        #pragma unroll
        for (int np = 0; np < 4; np++)
            boff[np] = (ncol0 + np * 16 + nrow) * HPITCH + ncol;
    }

    auto prefetchA = [&](int c) {
        if ((tid & 7) == 0) {
            int r = tid >> 3;
            #pragma unroll
            for (int l = 0; l < 4; l++) {
                long gr = m0 + r + l * 32;
                if (gr < M)
                    asm volatile("prefetch.global.L2 [%0];"
                                 :: "l"(X + gr * FEAT + c * BKC) : "memory");
            }
        }
    };

    float4 areg[4];
    auto ldgA = [&](int c) {
        #pragma unroll
        for (int l = 0; l < 4; l++) {
            int idx = tid + l * 256;
            int r = idx >> 3, j = idx & 7;
            long gr = m0 + r;
            areg[l] = (gr < M) ? *(const float4*)(X + gr * FEAT + c * BKC + j * 4)
                               : make_float4(0.f, 0.f, 0.f, 0.f);
        }
    };
    auto stsA = [&](int s) {
        #pragma unroll
        for (int l = 0; l < 4; l++) {
            int idx = tid + l * 256;
            int r = idx >> 3, j = idx & 7;
            __half2* p = (__half2*)(As + s * STAGEH + r * HPITCH + j * 4);
            p[0] = __floats2half2_rn(areg[l].x, areg[l].y);
            p[1] = __floats2half2_rn(areg[l].z, areg[l].w);
        }
    };
    auto cpB = [&](int c, int s) {
        #pragma unroll
        for (int l = 0; l < 2; l++) {
            int idx = tid + l * 256;
            int n = idx >> 2, j = idx & 3;
            cp_async16(bs_base + (s * STAGEH + n * HPITCH + j * 8) * 2,
                       g_wt16 + (long)n * FEAT + c * BKC + j * 8, 16);
        }
        CP_COMMIT();
    };

    float acc[2][8][4];
    #pragma unroll
    for (int mt = 0; mt < 2; mt++)
        #pragma unroll
        for (int nt = 0; nt < 8; nt++)
            #pragma unroll
            for (int q = 0; q < 4; q++) acc[mt][nt][q] = 0.0f;

    ldgA(0);
    cpB(0, 0);
    prefetchA(1);
    prefetchA(2);
    stsA(0);

    for (int c = 0; c < NCH; c++) {
        const int s = c & 1;
        if (c + 1 < NCH) {
            ldgA(c + 1);
            cpB(c + 1, s ^ 1);
            if (c + 2 < NCH) prefetchA(c + 2);
            CP_WAIT(1);
        } else {
            CP_WAIT(0);
        }
        __syncthreads();

        const uint32_t abase = as_base + s * STAGEH * 2;
        const uint32_t bbase = bs_base + s * STAGEH * 2;

        #pragma unroll
        for (int ks = 0; ks < 2; ks++) {
            const int k0h = ks * 16 * 2;
            uint32_t a[2][4], b[8][2];
            #pragma unroll
            for (int mt = 0; mt < 2; mt++)
                ldsm_x4(a[mt][0], a[mt][1], a[mt][2], a[mt][3],
                        abase + aoff[mt] * 2 + k0h);
            #pragma unroll
            for (int np = 0; np < 4; np++)
                ldsm_x4(b[2*np][0], b[2*np][1], b[2*np+1][0], b[2*np+1][1],
                        bbase + boff[np] * 2 + k0h);
            #pragma unroll
            for (int mt = 0; mt < 2; mt++)
                #pragma unroll
                for (int nt = 0; nt < 8; nt++)
                    asm volatile(
                        "mma.sync.aligned.m16n8k16.row.col.f32.f16.f16.f32 "
                        "{%0,%1,%2,%3}, {%4,%5,%6,%7}, {%8,%9}, {%0,%1,%2,%3};"
                        : "+f"(acc[mt][nt][0]), "+f"(acc[mt][nt][1]),
                          "+f"(acc[mt][nt][2]), "+f"(acc[mt][nt][3])
                        : "r"(a[mt][0]), "r"(a[mt][1]), "r"(a[mt][2]), "r"(a[mt][3]),
                          "r"(b[nt][0]), "r"(b[nt][1]));
        }
        __syncthreads();
        if (c + 1 < NCH) stsA(s ^ 1);
    }

    #pragma unroll
    for (int mt = 0; mt < 2; mt++) {
        long r0 = m0 + mrow0 + mt * 16 + grp;
        long r1 = r0 + 8;
        #pragma unroll
        for (int nt = 0; nt < 8; nt++) {
            int col = ncol0 + nt * 8 + 2 * tig;
            if (r0 < M)
                *(__half2*)(g_h + r0 * HID + col) =
                    __floats2half2_rn(acc[mt][nt][0], acc[mt][nt][1]);
            if (r1 < M)
                *(__half2*)(g_h + r1 * HID + col) =
                    __floats2half2_rn(acc[mt][nt][2], acc[mt][nt][3]);
        }
    }
}

// ---------------------------------------------------------------------------
// Bucketed adjacency fill: 2 edges per thread, vectorized index loads.
// ---------------------------------------------------------------------------
__global__ void fill_kernel(const void* __restrict__ ei, int E) {
    int t = blockIdx.x * blockDim.x + threadIdx.x;
    long e0 = (long)t * 2;
    if (e0 >= E) return;
    int is64 = g_is64;

    int r0, r1, c0, c1;
    bool two = (e0 + 1 < E);
    if (is64) {
        const long long* p = (const long long*)ei;
        if (two) {
            longlong2 rv = *(const longlong2*)(p + e0);
            longlong2 cv = *(const longlong2*)(p + E + e0);
            r0 = (int)rv.x; r1 = (int)rv.y; c0 = (int)cv.x; c1 = (int)cv.y;
        } else {
            r0 = (int)p[e0]; c0 = (int)p[E + e0]; r1 = -1; c1 = -1;
        }
    } else {
        const int* p = (const int*)ei;
        if (two) {
            int2 rv = *(const int2*)(p + e0);
            int2 cv = *(const int2*)(p + E + e0);
            r0 = rv.x; r1 = rv.y; c0 = cv.x; c1 = cv.y;
        } else {
            r0 = p[e0]; c0 = p[E + e0]; r1 = -1; c1 = -1;
        }
    }

    if ((unsigned)r0 < (unsigned)N_NODES && (unsigned)c0 < (unsigned)N_NODES) {
        int pos = atomicAdd(&g_cur[r0], 1);
        if (pos < BSLOT) g_bkt[(long)r0 * BSLOT + pos] = c0;
    }
    if (two && (unsigned)r1 < (unsigned)N_NODES && (unsigned)c1 < (unsigned)N_NODES) {
        int pos = atomicAdd(&g_cur[r1], 1);
        if (pos < BSLOT) g_bkt[(long)r1 * BSLOT + pos] = c1;
    }
}

__global__ void invsqrt_kernel() {
    int i = blockIdx.x * blockDim.x + threadIdx.x;
    if (i >= N_NODES) return;
    int c = g_cur[i];
    g_cnt[i] = c < BSLOT ? c : BSLOT;
    g_dis[i] = (c > 0) ? rsqrtf((float)c) : 0.0f;
}

// ---------------------------------------------------------------------------
// Aggregate: one warp per node; paired edges (lanes 0-15 edge j, 16-31 edge
// j+1), uint4 gathers (8 cols/lane), fp32 accumulate, cross-half combine.
// out[r] = bias + dis[r] * sum_c dis[c] * h[c]
// ---------------------------------------------------------------------------
__global__ void __launch_bounds__(256) agg_kernel(float* __restrict__ out,
                                                  const float* __restrict__ bias) {
    int r    = blockIdx.x * 8 + (threadIdx.x >> 5);
    int lane = threadIdx.x & 31;
    if (r >= N_NODES) return;

    const int   cnt = g_cnt[r];
    const float dr  = g_dis[r];
    const int*  row = g_bkt + (long)r * BSLOT;

    const int half    = lane >> 4;        // 0: even edges, 1: odd edges
    const int sublane = lane & 15;        // owns cols sublane*8 .. +7

    float acc[8];
    #pragma unroll
    for (int q = 0; q < 8; q++) acc[q] = 0.0f;

    for (int base = 0; base < cnt; base += 32) {
        int  k  = base + lane;
        bool ok = k < cnt;
        int  c  = ok ? row[k] : 0;
        float w = ok ? g_dis[c] : 0.0f;
        int nn = cnt - base; if (nn > 32) nn = 32;
        #pragma unroll 2
        for (int j = 0; j < nn; j += 2) {
            int   c0 = __shfl_sync(0xffffffffu, c, j);
            float w0 = __shfl_sync(0xffffffffu, w, j);
            int   c1 = __shfl_sync(0xffffffffu, c, j + 1);  // j+1<=31; zero-padded
            float w1 = __shfl_sync(0xffffffffu, w, j + 1);
            int   mc = half ? c1 : c0;
            float mw = half ? w1 : w0;
            uint4 u = *(const uint4*)(g_h + (long)mc * HID + sublane * 8);
            float2 p0 = __half22float2(*(const __half2*)&u.x);
            float2 p1 = __half22float2(*(const __half2*)&u.y);
            float2 p2 = __half22float2(*(const __half2*)&u.z);
            float2 p3 = __half22float2(*(const __half2*)&u.w);
            acc[0] = fmaf(mw, p0.x, acc[0]);
            acc[1] = fmaf(mw, p0.y, acc[1]);
            acc[2] = fmaf(mw, p1.x, acc[2]);
            acc[3] = fmaf(mw, p1.y, acc[3]);
            acc[4] = fmaf(mw, p2.x, acc[4]);
            acc[5] = fmaf(mw, p2.y, acc[5]);
            acc[6] = fmaf(mw, p3.x, acc[6]);
            acc[7] = fmaf(mw, p3.y, acc[7]);
        }
    }

    // combine even/odd halves
    #pragma unroll
    for (int q = 0; q < 8; q++)
        acc[q] += __shfl_xor_sync(0xffffffffu, acc[q], 16);

    if (half == 0) {
        const float* bp = bias + sublane * 8;
        float* op = out + (long)r * HID + sublane * 8;
        float4 b0 = *(const float4*)(bp);
        float4 b1 = *(const float4*)(bp + 4);
        *(float4*)(op) = make_float4(fmaf(dr, acc[0], b0.x), fmaf(dr, acc[1], b0.y),
                                     fmaf(dr, acc[2], b0.z), fmaf(dr, acc[3], b0.w));
        *(float4*)(op + 4) = make_float4(fmaf(dr, acc[4], b1.x), fmaf(dr, acc[5], b1.y),
                                         fmaf(dr, acc[6], b1.z), fmaf(dr, acc[7], b1.w));
    }
}

// ---------------------------------------------------------------------------
extern "C" void kernel_launch(void* const* d_in, const int* in_sizes, int n_in,
                              void* d_out, int out_size) {
    const float* x    = (const float*)d_in[0];
    const void*  ei   = d_in[1];
    const float* W    = (const float*)d_in[2];
    const float* bias = (const float*)d_in[3];
    float*       out  = (float*)d_out;

    const int E = in_sizes[1] / 2;

    // fork immediately: entire topology branch on side stream
    cudaEventRecord(g_ss.fork, 0);
    cudaStreamWaitEvent(g_ss.s, g_ss.fork, 0);
    detect_zero_kernel<<<(N_NODES + 255) / 256, 256, 0, g_ss.s>>>(ei, E);
    fill_kernel<<<(E / 2 + 255) / 256, 256, 0, g_ss.s>>>(ei, E);
    invsqrt_kernel<<<(N_NODES + 255) / 256, 256, 0, g_ss.s>>>();

    // main stream: transpose + GEMM (concurrent with topology branch)
    transpose_kernel<<<(FEAT * HID + 255) / 256, 256>>>(W);
    gemm_mma_kernel<<<(N_NODES + 127) / 128, 256>>>(x, N_NODES);

    // join, then aggregate
    cudaEventRecord(g_ss.join, g_ss.s);
    cudaStreamWaitEvent(0, g_ss.join, 0);
    agg_kernel<<<(N_NODES + 7) / 8, 256>>>(out, bias);
}